// round 7
// baseline (speedup 1.0000x reference)
#include <cuda_runtime.h>

#define NSAMP 65536
#define HALF_N (NSAMP / 2)
#define EPSF 1e-8f
#define TOTAL_WARPS 4096
#define BLOCK_THREADS 128
#define NBLOCKS (TOTAL_WARPS / (BLOCK_THREADS / 32))

// Warp-per-2-samples (ILP-2) register-resident persistent kernel.
// Lane l -> (o = l>>1, i-half h = l&1); lane owns pairs (o, i = h*8+k), k=0..7.
// Two independent samples (n, n+32768) are processed interleaved so every
// latency chain (shfl butterflies, MUFU, FMA chains) has a sibling to overlap.
// Quaternions persist in registers (32); trans lives in shared (LDS.128
// amortized over both samples).

__device__ __forceinline__ float fastrcp(float d) {
    float r;
    asm("rcp.approx.f32 %0, %1;" : "=f"(r) : "f"(d));
    return r;
}

__global__ void __launch_bounds__(BLOCK_THREADS, 3)
caps_quat_kernel(const float* __restrict__ x,
                 const float* __restrict__ quats,
                 const float* __restrict__ scale,
                 const float* __restrict__ trans,
                 const float* __restrict__ bias,
                 const float* __restrict__ beta,
                 const float* __restrict__ alpha,
                 float* __restrict__ out)
{
    __shared__ float4 sT[8 * 32];     // [k][lane] -> (t1, t2, t3, 0)

    const int tid  = threadIdx.x;
    const int lane = tid & 31;
    const int h    = lane & 1;       // i-half
    const int o    = lane >> 1;      // output capsule

    // ---- stage translations into shared ----
    for (int s = tid; s < 256; s += BLOCK_THREADS) {
        const int kp = s >> 5, lp = s & 31;
        const int pi = (lp >> 1) * 16 + ((lp & 1) << 3) + kp;
        sT[s] = make_float4(trans[pi * 3 + 0], trans[pi * 3 + 1], trans[pi * 3 + 2], 0.0f);
    }

    // ---- persistent per-lane constants: scaled quaternions (32 regs) ----
    float qw[8], qx[8], qy[8], qz[8];
    const float4* __restrict__ q4 = (const float4*)quats;
#pragma unroll
    for (int k = 0; k < 8; k++) {
        const int pi = o * 16 + h * 8 + k;
        const float4 q = __ldg(&q4[pi]);
        const float f = rsqrtf(fmaf(q.x, q.x, fmaf(q.y, q.y, fmaf(q.z, q.z, q.w * q.w))) + EPSF)
                        * __ldg(&scale[pi]);
        qw[k] = q.x * f; qx[k] = q.y * f; qy[k] = q.z * f; qz[k] = q.w * f;
    }
    const float bet = __ldg(&beta[o]);
    const float ab  = __ldg(&alpha[o]) + __ldg(&bias[o]);

    __syncthreads();

    const float4* __restrict__ x4   = (const float4*)x;
    float4* __restrict__       out4 = (float4*)out;

    const int warp = blockIdx.x * (BLOCK_THREADS / 32) + (tid >> 5);
    const bool b4  = (lane & 4)  != 0;
    const bool b8  = (lane & 8)  != 0;
    const bool b16 = (lane & 16) != 0;

#pragma unroll 1
    for (int n = warp; n < HALF_N; n += TOTAL_WARPS) {
        // ---- votes for both samples (trans LDS shared between them) ----
        float vw[2][8], vx[2][8], vy[2][8], vz[2][8];
#pragma unroll
        for (int k = 0; k < 8; k++) {
            const float4 T = sT[k * 32 + lane];
#pragma unroll
            for (int m = 0; m < 2; m++) {
                const float4 X = __ldg(&x4[(n + m * HALF_N) * 16 + h * 8 + k]);
                vw[m][k] = fmaf(qw[k], X.x, fmaf(-qx[k], X.y, fmaf(-qy[k], X.z, -qz[k] * X.w)));
                vx[m][k] = fmaf(qw[k], X.y, fmaf( qx[k], X.x, fmaf( qy[k], X.w, fmaf(-qz[k], X.z, T.x))));
                vy[m][k] = fmaf(qw[k], X.z, fmaf(-qx[k], X.w, fmaf( qy[k], X.x, fmaf( qz[k], X.y, T.y))));
                vz[m][k] = fmaf(qw[k], X.w, fmaf( qx[k], X.z, fmaf(-qy[k], X.y, fmaf( qz[k], X.x, T.z))));
            }
        }

        // ---- dynamic routing, 3 iterations, both samples interleaved ----
        float bb[2][8];
        float s0[2], s1[2], s2[2], s3[2], v0[2], v1[2], v2[2], v3[2], n2[2];

#pragma unroll
        for (int iter = 0; iter < 3; iter++) {
            if (iter == 0) {
#pragma unroll
                for (int m = 0; m < 2; m++) {
                    float a0 = vw[m][0], a1 = vx[m][0], a2 = vy[m][0], a3 = vz[m][0];
#pragma unroll
                    for (int k = 1; k < 8; k++) {
                        a0 += vw[m][k]; a1 += vx[m][k]; a2 += vy[m][k]; a3 += vz[m][k];
                    }
                    s0[m] = a0 * 0.0625f; s1[m] = a1 * 0.0625f;
                    s2[m] = a2 * 0.0625f; s3[m] = a3 * 0.0625f;
                }
            } else {
                // softmax over o (no max-shift; |b| bounded, f32-safe)
                float e[2][8], r[2][8];
#pragma unroll
                for (int m = 0; m < 2; m++)
#pragma unroll
                    for (int k = 0; k < 8; k++) { e[m][k] = __expf(bb[m][k]); r[m][k] = e[m][k]; }

                // reduce-scatter of den over o-lanes (masks 16,8,4,2), m-interleaved
#pragma unroll
                for (int j = 0; j < 4; j++)
#pragma unroll
                    for (int m = 0; m < 2; m++) {
                        const float snd = b16 ? r[m][j] : r[m][j + 4];
                        const float rcv = __shfl_xor_sync(0xffffffffu, snd, 16);
                        r[m][j] = (b16 ? r[m][j + 4] : r[m][j]) + rcv;
                    }
#pragma unroll
                for (int j = 0; j < 2; j++)
#pragma unroll
                    for (int m = 0; m < 2; m++) {
                        const float snd = b8 ? r[m][j] : r[m][j + 2];
                        const float rcv = __shfl_xor_sync(0xffffffffu, snd, 8);
                        r[m][j] = (b8 ? r[m][j + 2] : r[m][j]) + rcv;
                    }
#pragma unroll
                for (int m = 0; m < 2; m++) {
                    const float snd = b4 ? r[m][0] : r[m][1];
                    const float rcv = __shfl_xor_sync(0xffffffffu, snd, 4);
                    r[m][0] = (b4 ? r[m][1] : r[m][0]) + rcv;
                }
#pragma unroll
                for (int m = 0; m < 2; m++)
                    r[m][0] += __shfl_xor_sync(0xffffffffu, r[m][0], 2);

                float rd[2];
#pragma unroll
                for (int m = 0; m < 2; m++) rd[m] = fastrcp(r[m][0]);

                // all-gather of reciprocal dens (masks 4,8,16), m-interleaved
                float rden[2][8];
#pragma unroll
                for (int m = 0; m < 2; m++) {
                    float g0, g1, g2, g3;
                    {
                        const float p = __shfl_xor_sync(0xffffffffu, rd[m], 4);
                        g0 = b4 ? p : rd[m];
                        g1 = b4 ? rd[m] : p;
                    }
                    {
                        const float p0 = __shfl_xor_sync(0xffffffffu, g0, 8);
                        const float p1 = __shfl_xor_sync(0xffffffffu, g1, 8);
                        g2 = b8 ? g0 : p0;  g3 = b8 ? g1 : p1;
                        g0 = b8 ? p0 : g0;  g1 = b8 ? p1 : g1;
                    }
                    {
                        const float p0 = __shfl_xor_sync(0xffffffffu, g0, 16);
                        const float p1 = __shfl_xor_sync(0xffffffffu, g1, 16);
                        const float p2 = __shfl_xor_sync(0xffffffffu, g2, 16);
                        const float p3 = __shfl_xor_sync(0xffffffffu, g3, 16);
                        rden[m][0] = b16 ? p0 : g0;  rden[m][1] = b16 ? p1 : g1;
                        rden[m][2] = b16 ? p2 : g2;  rden[m][3] = b16 ? p3 : g3;
                        rden[m][4] = b16 ? g0 : p0;  rden[m][5] = b16 ? g1 : p1;
                        rden[m][6] = b16 ? g2 : p2;  rden[m][7] = b16 ? g3 : p3;
                    }
                }

                // c = e * rden, weighted einsum
#pragma unroll
                for (int m = 0; m < 2; m++) {
                    float a0 = 0.f, a1 = 0.f, a2 = 0.f, a3 = 0.f;
#pragma unroll
                    for (int k = 0; k < 8; k++) {
                        const float c = e[m][k] * rden[m][k];
                        a0 = fmaf(c, vw[m][k], a0);
                        a1 = fmaf(c, vx[m][k], a1);
                        a2 = fmaf(c, vy[m][k], a2);
                        a3 = fmaf(c, vz[m][k], a3);
                    }
                    s0[m] = a0; s1[m] = a1; s2[m] = a2; s3[m] = a3;
                }
            }

            // fold the two i-halves (m-interleaved shfls)
#pragma unroll
            for (int m = 0; m < 2; m++) {
                s0[m] += __shfl_xor_sync(0xffffffffu, s0[m], 1);
                s1[m] += __shfl_xor_sync(0xffffffffu, s1[m], 1);
                s2[m] += __shfl_xor_sync(0xffffffffu, s2[m], 1);
                s3[m] += __shfl_xor_sync(0xffffffffu, s3[m], 1);
            }

            // squash
#pragma unroll
            for (int m = 0; m < 2; m++) {
                n2[m] = fmaf(s0[m], s0[m], fmaf(s1[m], s1[m], fmaf(s2[m], s2[m], s3[m] * s3[m])));
                const float fac = n2[m] * fastrcp(1.0f + n2[m]) * rsqrtf(n2[m] + EPSF);
                v0[m] = s0[m] * fac; v1[m] = s1[m] * fac;
                v2[m] = s2[m] * fac; v3[m] = s3[m] * fac;
            }

            // agreement update (dead on the last iteration)
            if (iter == 0) {
#pragma unroll
                for (int m = 0; m < 2; m++)
#pragma unroll
                    for (int k = 0; k < 8; k++)
                        bb[m][k] = fmaf(v0[m], vw[m][k],
                                   fmaf(v1[m], vx[m][k],
                                   fmaf(v2[m], vy[m][k], v3[m] * vz[m][k])));
            } else if (iter == 1) {
#pragma unroll
                for (int m = 0; m < 2; m++)
#pragma unroll
                    for (int k = 0; k < 8; k++)
                        bb[m][k] = fmaf(v0[m], vw[m][k],
                                   fmaf(v1[m], vx[m][k],
                                   fmaf(v2[m], vy[m][k],
                                   fmaf(v3[m], vz[m][k], bb[m][k]))));
            }
        }

        // ---- activation + store (even lanes: one coalesced float4 per (n,o)) ----
#pragma unroll
        for (int m = 0; m < 2; m++) {
            const float norm_s = sqrtf(n2[m] + EPSF);
            const float z = fmaf(bet, norm_s, ab);
            const float a = fastrcp(1.0f + __expf(-z));
            if (h == 0) {
                out4[(n + m * HALF_N) * 16 + o] =
                    make_float4(v0[m] * a, v1[m] * a, v2[m] * a, v3[m] * a);
            }
        }
    }
}

extern "C" void kernel_launch(void* const* d_in, const int* in_sizes, int n_in,
                              void* d_out, int out_size)
{
    const float* x     = (const float*)d_in[0];
    const float* quats = (const float*)d_in[1];
    const float* scale = (const float*)d_in[2];
    const float* trans = (const float*)d_in[3];
    const float* bias  = (const float*)d_in[4];
    const float* beta  = (const float*)d_in[5];
    const float* alpha = (const float*)d_in[6];

    caps_quat_kernel<<<NBLOCKS, BLOCK_THREADS>>>(x, quats, scale, trans, bias, beta, alpha,
                                                 (float*)d_out);
}

// round 8
// speedup vs baseline: 1.2242x; 1.2242x over previous
#include <cuda_runtime.h>

#define NSAMP 65536
#define EPSF 1e-8f
#define BLOCK_THREADS 128
#define NBLOCKS 592                    // 4 CTAs/SM x 148 SMs: single resident wave
#define TOTAL_WARPS (NBLOCKS * (BLOCK_THREADS / 32))

// Warp-per-sample, register-resident, single-wave persistent kernel.
// Lane l -> (o = l>>1, i-half h = l&1); lane owns pairs (o, i = h*8+k), k=0..7.
// Softmax denominator: reduce-scatter over o-lanes + single rcp + all-gather.

__device__ __forceinline__ float fastrcp(float d) {
    float r;
    asm("rcp.approx.f32 %0, %1;" : "=f"(r) : "f"(d));
    return r;
}

__global__ void __launch_bounds__(BLOCK_THREADS, 4)
caps_quat_kernel(const float* __restrict__ x,
                 const float* __restrict__ quats,
                 const float* __restrict__ scale,
                 const float* __restrict__ trans,
                 const float* __restrict__ bias,
                 const float* __restrict__ beta,
                 const float* __restrict__ alpha,
                 float* __restrict__ out)
{
    const int lane = threadIdx.x & 31;
    const int warp = blockIdx.x * (BLOCK_THREADS / 32) + (threadIdx.x >> 5);
    const int h    = lane & 1;       // i-half
    const int o    = lane >> 1;      // output capsule

    // ---- one-time prologue: scaled quaternion + trans for this lane's 8 pairs ----
    float qw[8], qx[8], qy[8], qz[8], t1[8], t2[8], t3[8];
    const float4* __restrict__ q4 = (const float4*)quats;
#pragma unroll
    for (int k = 0; k < 8; k++) {
        const int pi = o * 16 + h * 8 + k;
        const float4 q = __ldg(&q4[pi]);
        const float f = rsqrtf(fmaf(q.x, q.x, fmaf(q.y, q.y, fmaf(q.z, q.z, q.w * q.w))) + EPSF)
                        * __ldg(&scale[pi]);
        qw[k] = q.x * f; qx[k] = q.y * f; qy[k] = q.z * f; qz[k] = q.w * f;
        t1[k] = __ldg(&trans[pi * 3 + 0]);
        t2[k] = __ldg(&trans[pi * 3 + 1]);
        t3[k] = __ldg(&trans[pi * 3 + 2]);
    }
    const float bet = __ldg(&beta[o]);
    const float ab  = __ldg(&alpha[o]) + __ldg(&bias[o]);

    const float4* __restrict__ x4   = (const float4*)x;
    float4* __restrict__       out4 = (float4*)out;

    const bool b4  = (lane & 4)  != 0;
    const bool b8  = (lane & 8)  != 0;
    const bool b16 = (lane & 16) != 0;

#pragma unroll 1
    for (int n = warp; n < NSAMP; n += TOTAL_WARPS) {
        // ---- votes: Hamilton product from quaternion registers ----
        float vw[8], vx[8], vy[8], vz[8];
#pragma unroll
        for (int k = 0; k < 8; k++) {
            const float4 X = __ldg(&x4[n * 16 + h * 8 + k]);
            vw[k] = fmaf(qw[k], X.x, fmaf(-qx[k], X.y, fmaf(-qy[k], X.z, -qz[k] * X.w)));
            vx[k] = fmaf(qw[k], X.y, fmaf( qx[k], X.x, fmaf( qy[k], X.w, fmaf(-qz[k], X.z, t1[k]))));
            vy[k] = fmaf(qw[k], X.z, fmaf(-qx[k], X.w, fmaf( qy[k], X.x, fmaf( qz[k], X.y, t2[k]))));
            vz[k] = fmaf(qw[k], X.w, fmaf( qx[k], X.z, fmaf(-qy[k], X.y, fmaf( qz[k], X.x, t3[k]))));
        }

        // ---- dynamic routing, 3 iterations ----
        float bb[8];
        float s0, s1, s2, s3, v0, v1, v2, v3, n2 = 0.0f;

#pragma unroll
        for (int iter = 0; iter < 3; iter++) {
            if (iter == 0) {
                // b == 0 -> uniform coupling c = 1/16
                s0 = vw[0]; s1 = vx[0]; s2 = vy[0]; s3 = vz[0];
#pragma unroll
                for (int k = 1; k < 8; k++) {
                    s0 += vw[k]; s1 += vx[k]; s2 += vy[k]; s3 += vz[k];
                }
                s0 *= 0.0625f; s1 *= 0.0625f; s2 *= 0.0625f; s3 *= 0.0625f;
            } else {
                // softmax over o (no max-shift; |b| bounded, f32-safe).
                float e[8], r[8];
#pragma unroll
                for (int k = 0; k < 8; k++) { e[k] = __expf(bb[k]); r[k] = e[k]; }

                // --- reduce-scatter of den over o-lanes (masks 16,8,4,2) ---
#pragma unroll
                for (int j = 0; j < 4; j++) {
                    const float snd = b16 ? r[j] : r[j + 4];
                    const float rcv = __shfl_xor_sync(0xffffffffu, snd, 16);
                    r[j] = (b16 ? r[j + 4] : r[j]) + rcv;
                }
#pragma unroll
                for (int j = 0; j < 2; j++) {
                    const float snd = b8 ? r[j] : r[j + 2];
                    const float rcv = __shfl_xor_sync(0xffffffffu, snd, 8);
                    r[j] = (b8 ? r[j + 2] : r[j]) + rcv;
                }
                {
                    const float snd = b4 ? r[0] : r[1];
                    const float rcv = __shfl_xor_sync(0xffffffffu, snd, 4);
                    r[0] = (b4 ? r[1] : r[0]) + rcv;
                }
                r[0] += __shfl_xor_sync(0xffffffffu, r[0], 2);

                // one reciprocal per lane
                const float rd = fastrcp(r[0]);

                // --- all-gather of reciprocal dens (masks 4,8,16) ---
                float g0, g1, g2, g3, rden[8];
                {
                    const float p = __shfl_xor_sync(0xffffffffu, rd, 4);
                    g0 = b4 ? p : rd;
                    g1 = b4 ? rd : p;
                }
                {
                    const float p0 = __shfl_xor_sync(0xffffffffu, g0, 8);
                    const float p1 = __shfl_xor_sync(0xffffffffu, g1, 8);
                    g2 = b8 ? g0 : p0;  g3 = b8 ? g1 : p1;
                    g0 = b8 ? p0 : g0;  g1 = b8 ? p1 : g1;
                }
                {
                    const float p0 = __shfl_xor_sync(0xffffffffu, g0, 16);
                    const float p1 = __shfl_xor_sync(0xffffffffu, g1, 16);
                    const float p2 = __shfl_xor_sync(0xffffffffu, g2, 16);
                    const float p3 = __shfl_xor_sync(0xffffffffu, g3, 16);
                    rden[0] = b16 ? p0 : g0;  rden[1] = b16 ? p1 : g1;
                    rden[2] = b16 ? p2 : g2;  rden[3] = b16 ? p3 : g3;
                    rden[4] = b16 ? g0 : p0;  rden[5] = b16 ? g1 : p1;
                    rden[6] = b16 ? g2 : p2;  rden[7] = b16 ? g3 : p3;
                }

                s0 = s1 = s2 = s3 = 0.0f;
#pragma unroll
                for (int k = 0; k < 8; k++) {
                    const float c = e[k] * rden[k];
                    s0 = fmaf(c, vw[k], s0);
                    s1 = fmaf(c, vx[k], s1);
                    s2 = fmaf(c, vy[k], s2);
                    s3 = fmaf(c, vz[k], s3);
                }
            }
            // fold the two i-halves
            s0 += __shfl_xor_sync(0xffffffffu, s0, 1);
            s1 += __shfl_xor_sync(0xffffffffu, s1, 1);
            s2 += __shfl_xor_sync(0xffffffffu, s2, 1);
            s3 += __shfl_xor_sync(0xffffffffu, s3, 1);

            // squash
            n2 = fmaf(s0, s0, fmaf(s1, s1, fmaf(s2, s2, s3 * s3)));
            const float fac = n2 * fastrcp(1.0f + n2) * rsqrtf(n2 + EPSF);
            v0 = s0 * fac; v1 = s1 * fac; v2 = s2 * fac; v3 = s3 * fac;

            // agreement update (iter0: bb was zero -> pure assignment; dead at iter2)
            if (iter == 0) {
#pragma unroll
                for (int k = 0; k < 8; k++)
                    bb[k] = fmaf(v0, vw[k], fmaf(v1, vx[k], fmaf(v2, vy[k], v3 * vz[k])));
            } else if (iter == 1) {
#pragma unroll
                for (int k = 0; k < 8; k++)
                    bb[k] = fmaf(v0, vw[k], fmaf(v1, vx[k], fmaf(v2, vy[k], fmaf(v3, vz[k], bb[k]))));
            }
        }

        // ---- activation + store (even lanes: one coalesced float4 per (n,o)) ----
        const float norm_s = sqrtf(n2 + EPSF);
        const float z = fmaf(bet, norm_s, ab);
        const float a = fastrcp(1.0f + __expf(-z));

        if (h == 0) {
            out4[n * 16 + o] = make_float4(v0 * a, v1 * a, v2 * a, v3 * a);
        }
    }
}

extern "C" void kernel_launch(void* const* d_in, const int* in_sizes, int n_in,
                              void* d_out, int out_size)
{
    const float* x     = (const float*)d_in[0];
    const float* quats = (const float*)d_in[1];
    const float* scale = (const float*)d_in[2];
    const float* trans = (const float*)d_in[3];
    const float* bias  = (const float*)d_in[4];
    const float* beta  = (const float*)d_in[5];
    const float* alpha = (const float*)d_in[6];

    caps_quat_kernel<<<NBLOCKS, BLOCK_THREADS>>>(x, quats, scale, trans, bias, beta, alpha,
                                                 (float*)d_out);
}